// round 5
// baseline (speedup 1.0000x reference)
#include <cuda_runtime.h>
#include <math.h>

#define NN 100000
#define EE 600000
#define FF 128
#define CC 64
#define LT 8   // node tile in linear kernel

// ---------------- scratch (static __device__, no allocations) ----------------
__device__ float g_X0[(size_t)NN * FF];
__device__ float g_X1[(size_t)NN * FF];
__device__ float g_deg[NN];        // degree, then dinv in place
__device__ float g_norm[EE];       // sigmoid(ew) masked
__device__ float g_s[FF];          // feature gate
__device__ int   g_cnt[NN];        // in-degree counts
__device__ int   g_rowptr[NN + 1]; // CSR row pointers (by dst node)
__device__ int   g_cursor[NN];     // fill cursors
__device__ int   g_csr_src[EE];    // CSR: source node per edge slot
__device__ float g_csr_w[EE];      // CSR: norm weight per edge slot
__device__ int   g_is64;

// ---------------- dtype detection: int64 vs int32 edge_index ----------------
__global__ void k_detect(const int* __restrict__ w) {
    __shared__ int nz;
    if (threadIdx.x == 0) nz = 0;
    __syncthreads();
    int found = 0;
    for (int i = threadIdx.x; i < 1024; i += blockDim.x)
        if (w[2 * i + 1] != 0) found = 1;
    if (found) atomicOr(&nz, 1);
    __syncthreads();
    if (threadIdx.x == 0) g_is64 = nz ? 0 : 1;
}

__device__ __forceinline__ long long eidx(const void* p, long long i, int is64) {
    if (is64) return ((const long long*)p)[i];
    return (long long)((const int*)p)[i];
}

__device__ __forceinline__ float sigm(float w) {
    return 1.0f / (1.0f + __expf(-w));
}

// ---------------- feature gate -----------------------------------------------
__global__ void k_feat_gate(const float* __restrict__ xw) {
    int f = threadIdx.x;
    if (f < FF) {
        float w = xw[f];
        g_s[f] = (fabsf(w) > 0.0f) ? sigm(w) : 0.0f;
    }
}

// ---------------- X0 = x * s ; deg = 1.0 (self loop) ; cnt = 0 ---------------
__global__ void k_scale_x(const float* __restrict__ x) {
    int idx = blockIdx.x * blockDim.x + threadIdx.x;   // float4 index
    if (idx < NN * FF / 4) {
        float4 v = ((const float4*)x)[idx];
        int f = (idx & (FF / 4 - 1)) * 4;
        v.x *= g_s[f]; v.y *= g_s[f + 1]; v.z *= g_s[f + 2]; v.w *= g_s[f + 3];
        ((float4*)g_X0)[idx] = v;
        if (idx < NN) { g_deg[idx] = 1.0f; g_cnt[idx] = 0; }
    }
}

// ---------------- per-edge weight + degree + in-degree count -----------------
__global__ void k_edge_deg(const void* __restrict__ ei, const float* __restrict__ ew) {
    int e = blockIdx.x * blockDim.x + threadIdx.x;
    if (e < EE) {
        int is64 = g_is64;
        float w = ew[e];
        float s = (fabsf(w) > 0.0f) ? sigm(w) : 0.0f;
        g_norm[e] = s;
        int c = (int)eidx(ei, (long long)EE + e, is64);
        atomicAdd(&g_deg[c], s);
        atomicAdd(&g_cnt[c], 1);
    }
}

// ---------------- dinv = rsqrt(deg); deg >= 1 always -------------------------
__global__ void k_dinv() {
    int i = blockIdx.x * blockDim.x + threadIdx.x;
    if (i < NN) g_deg[i] = rsqrtf(g_deg[i]);
}

// ---------------- exclusive scan of g_cnt -> g_rowptr, g_cursor --------------
// single block, 1024 threads, contiguous chunks + Hillis-Steele block scan.
__global__ void k_scan() {
    __shared__ int ssum[1024];
    const int T = 1024;
    const int CH = (NN + T - 1) / T;     // 98
    int tid = threadIdx.x;
    int lo = tid * CH;
    int hi = lo + CH; if (hi > NN) hi = NN;
    int s = 0;
    for (int i = lo; i < hi; i++) s += g_cnt[i];
    ssum[tid] = s;
    __syncthreads();
    // inclusive Hillis-Steele (read, sync, write, sync)
    for (int off = 1; off < T; off <<= 1) {
        int add = (tid >= off) ? ssum[tid - off] : 0;
        __syncthreads();
        ssum[tid] += add;
        __syncthreads();
    }
    int run = (tid > 0) ? ssum[tid - 1] : 0;   // exclusive prefix of chunk
    for (int i = lo; i < hi; i++) {
        g_rowptr[i] = run;
        g_cursor[i] = run;
        run += g_cnt[i];
    }
    if (tid == T - 1) g_rowptr[NN] = run;
}

// ---------------- CSR fill: slot per edge, fused norm computation ------------
__global__ void k_fill(const void* __restrict__ ei) {
    int e = blockIdx.x * blockDim.x + threadIdx.x;
    if (e < EE) {
        int is64 = g_is64;
        int r = (int)eidx(ei, e, is64);
        int c = (int)eidx(ei, (long long)EE + e, is64);
        int pos = atomicAdd(&g_cursor[c], 1);
        g_csr_src[pos] = r;
        g_csr_w[pos]   = g_deg[r] * g_norm[e] * g_deg[c];
    }
}

// ---------------- hop: warp-per-node CSR gather, self-loop fused -------------
// software-pipelined 2-deep: two row gathers in flight per warp.
__global__ void k_gather(int dir) {
    const float* __restrict__ src = dir ? g_X1 : g_X0;
    float*       __restrict__ dst = dir ? g_X0 : g_X1;
    int n = (blockIdx.x * blockDim.x + threadIdx.x) >> 5;
    int lane = threadIdx.x & 31;
    if (n >= NN) return;
    float d = g_deg[n];
    float dd = d * d;
    const float4* sv = (const float4*)src;
    float4 acc = sv[(size_t)n * (FF / 4) + lane];
    acc.x *= dd; acc.y *= dd; acc.z *= dd; acc.w *= dd;
    int beg = g_rowptr[n], end = g_rowptr[n + 1];
    int e = beg;
    // pairs: issue two index loads + two row loads before consuming
    for (; e + 2 <= end; e += 2) {
        int   s0 = __ldg(&g_csr_src[e]);
        int   s1 = __ldg(&g_csr_src[e + 1]);
        float w0 = __ldg(&g_csr_w[e]);
        float w1 = __ldg(&g_csr_w[e + 1]);
        float4 v0 = sv[(size_t)s0 * (FF / 4) + lane];
        float4 v1 = sv[(size_t)s1 * (FF / 4) + lane];
        acc.x += w0 * v0.x; acc.y += w0 * v0.y;
        acc.z += w0 * v0.z; acc.w += w0 * v0.w;
        acc.x += w1 * v1.x; acc.y += w1 * v1.y;
        acc.z += w1 * v1.z; acc.w += w1 * v1.w;
    }
    if (e < end) {
        int   s0 = __ldg(&g_csr_src[e]);
        float w0 = __ldg(&g_csr_w[e]);
        float4 v0 = sv[(size_t)s0 * (FF / 4) + lane];
        acc.x += w0 * v0.x; acc.y += w0 * v0.y;
        acc.z += w0 * v0.z; acc.w += w0 * v0.w;
    }
    ((float4*)(dst + (size_t)n * FF))[lane] = acc;
}

// ---------------- out = log_softmax(X @ W^T + b) -----------------------------
__global__ void k_linear(const float* __restrict__ W, const float* __restrict__ b,
                         float* __restrict__ out) {
    __shared__ float4 sW[CC * 33];        // row pad 33 float4 -> conflict-free
    __shared__ float  sx[LT][FF];
    __shared__ float  redm[2], reds[2];
    const float* X = g_X0;                // result of hop 2
    int tid = threadIdx.x;                // 0..63 == class
    for (int i = tid; i < CC * FF / 4; i += CC) {
        int c = i >> 5;
        int k4 = i & 31;
        sW[c * 33 + k4] = ((const float4*)W)[i];
    }
    float bias = b[tid];
    __syncthreads();

    for (int g = blockIdx.x; g < NN / LT; g += gridDim.x) {
        long long base = (long long)g * LT;
        for (int i = tid; i < LT * FF / 4; i += CC)
            ((float4*)&sx[0][0])[i] = ((const float4*)(X + base * FF))[i];
        __syncthreads();

        float acc[LT];
        #pragma unroll
        for (int t2 = 0; t2 < LT; t2++) acc[t2] = bias;
        const float4* wr = &sW[tid * 33];
        #pragma unroll
        for (int k4 = 0; k4 < FF / 4; k4++) {
            float4 w4 = wr[k4];
            #pragma unroll
            for (int t2 = 0; t2 < LT; t2++) {
                float4 x4 = ((const float4*)sx[t2])[k4];
                acc[t2] += w4.x * x4.x + w4.y * x4.y + w4.z * x4.z + w4.w * x4.w;
            }
        }

        #pragma unroll
        for (int t2 = 0; t2 < LT; t2++) {
            float v = acc[t2];
            float m = v;
            #pragma unroll
            for (int o = 16; o > 0; o >>= 1)
                m = fmaxf(m, __shfl_xor_sync(0xffffffffu, m, o));
            if ((tid & 31) == 0) redm[tid >> 5] = m;
            __syncthreads();
            m = fmaxf(redm[0], redm[1]);
            float ex = __expf(v - m);
            float ssum = ex;
            #pragma unroll
            for (int o = 16; o > 0; o >>= 1)
                ssum += __shfl_xor_sync(0xffffffffu, ssum, o);
            if ((tid & 31) == 0) reds[tid >> 5] = ssum;
            __syncthreads();
            float tot = reds[0] + reds[1];
            out[(base + t2) * CC + tid] = v - m - __logf(tot);
        }
        __syncthreads();
    }
}

// ---------------------------------------------------------------------------
extern "C" void kernel_launch(void* const* d_in, const int* in_sizes, int n_in,
                              void* d_out, int out_size) {
    const float* x  = (const float*)d_in[0];
    const void*  ei = d_in[1];
    const float* ew = (const float*)d_in[2];
    const float* xw = (const float*)d_in[3];
    const float* W  = (const float*)d_in[4];
    const float* b  = (const float*)d_in[5];
    float* out = (float*)d_out;

    const int THREADS = 256;
    const int nxf4 = NN * FF / 4;

    k_detect<<<1, 256>>>((const int*)ei);
    k_feat_gate<<<1, 128>>>(xw);
    k_scale_x<<<(nxf4 + THREADS - 1) / THREADS, THREADS>>>(x);
    k_edge_deg<<<(EE + THREADS - 1) / THREADS, THREADS>>>(ei, ew);
    k_dinv<<<(NN + THREADS - 1) / THREADS, THREADS>>>();
    k_scan<<<1, 1024>>>();
    k_fill<<<(EE + THREADS - 1) / THREADS, THREADS>>>(ei);

    // hop 1: X0 -> X1   hop 2: X1 -> X0   (warp per node)
    const int GB = (NN * 32 + THREADS - 1) / THREADS;
    k_gather<<<GB, THREADS>>>(0);
    k_gather<<<GB, THREADS>>>(1);

    k_linear<<<1480, CC>>>(W, b, out);
}

// round 6
// speedup vs baseline: 1.2323x; 1.2323x over previous
#include <cuda_runtime.h>
#include <math.h>

#define NN 100000
#define EE 600000
#define FF 128
#define CC 64

// ---------------- scratch (static __device__, no allocations) ----------------
__device__ float g_X0[(size_t)NN * CC];   // projected features (width 64)
__device__ float g_X1[(size_t)NN * CC];
__device__ float g_Wt[FF * CC];           // W'[k][c] = W[c][k] * s[k]
__device__ float g_deg[NN];               // degree, then dinv in place
__device__ float g_norm[EE];              // sigmoid(ew) masked
__device__ float g_s[FF];                 // feature gate
__device__ int   g_cnt[NN];               // in-degree counts
__device__ int   g_rowptr[NN + 1];        // CSR row pointers (by dst node)
__device__ int   g_cursor[NN];            // fill cursors
__device__ int   g_csr_src[EE];           // CSR: source node per edge slot
__device__ float g_csr_w[EE];             // CSR: norm weight per edge slot
__device__ int   g_is64;

// ---------------- dtype detection: int64 vs int32 edge_index ----------------
__global__ void k_detect(const int* __restrict__ w) {
    __shared__ int nz;
    if (threadIdx.x == 0) nz = 0;
    __syncthreads();
    int found = 0;
    for (int i = threadIdx.x; i < 1024; i += blockDim.x)
        if (w[2 * i + 1] != 0) found = 1;
    if (found) atomicOr(&nz, 1);
    __syncthreads();
    if (threadIdx.x == 0) g_is64 = nz ? 0 : 1;
}

__device__ __forceinline__ long long eidx(const void* p, long long i, int is64) {
    if (is64) return ((const long long*)p)[i];
    return (long long)((const int*)p)[i];
}

__device__ __forceinline__ float sigm(float w) {
    return 1.0f / (1.0f + __expf(-w));
}

// ---------------- feature gate -----------------------------------------------
__global__ void k_feat_gate(const float* __restrict__ xw) {
    int f = threadIdx.x;
    if (f < FF) {
        float w = xw[f];
        g_s[f] = (fabsf(w) > 0.0f) ? sigm(w) : 0.0f;
    }
}

// ---------------- W'[k][c] = W[c][k] * s[k] ----------------------------------
__global__ void k_wprep(const float* __restrict__ W) {
    int t = blockIdx.x * blockDim.x + threadIdx.x;   // t = c*128 + k
    if (t < CC * FF) {
        int c = t >> 7;
        int k = t & 127;
        g_Wt[k * CC + c] = W[t] * g_s[k];
    }
}

// ---------------- deg = 1.0 (self loop), cnt = 0 -----------------------------
__global__ void k_init() {
    int i = blockIdx.x * blockDim.x + threadIdx.x;
    if (i < NN) { g_deg[i] = 1.0f; g_cnt[i] = 0; }
}

// ---------------- per-edge weight + degree + in-degree count -----------------
__global__ void k_edge_deg(const void* __restrict__ ei, const float* __restrict__ ew) {
    int e = blockIdx.x * blockDim.x + threadIdx.x;
    if (e < EE) {
        int is64 = g_is64;
        float w = ew[e];
        float s = (fabsf(w) > 0.0f) ? sigm(w) : 0.0f;
        g_norm[e] = s;
        int c = (int)eidx(ei, (long long)EE + e, is64);
        atomicAdd(&g_deg[c], s);
        atomicAdd(&g_cnt[c], 1);
    }
}

// ---------------- dinv = rsqrt(deg); deg >= 1 always -------------------------
__global__ void k_dinv() {
    int i = blockIdx.x * blockDim.x + threadIdx.x;
    if (i < NN) g_deg[i] = rsqrtf(g_deg[i]);
}

// ---------------- exclusive scan of g_cnt -> g_rowptr, g_cursor --------------
__global__ void k_scan() {
    __shared__ int ssum[1024];
    const int T = 1024;
    const int CH = (NN + T - 1) / T;     // 98
    int tid = threadIdx.x;
    int lo = tid * CH;
    int hi = lo + CH; if (hi > NN) hi = NN;
    int s = 0;
    for (int i = lo; i < hi; i++) s += g_cnt[i];
    ssum[tid] = s;
    __syncthreads();
    for (int off = 1; off < T; off <<= 1) {
        int add = (tid >= off) ? ssum[tid - off] : 0;
        __syncthreads();
        ssum[tid] += add;
        __syncthreads();
    }
    int run = (tid > 0) ? ssum[tid - 1] : 0;
    for (int i = lo; i < hi; i++) {
        g_rowptr[i] = run;
        g_cursor[i] = run;
        run += g_cnt[i];
    }
    if (tid == T - 1) g_rowptr[NN] = run;
}

// ---------------- CSR fill: slot per edge, fused norm ------------------------
__global__ void k_fill(const void* __restrict__ ei) {
    int e = blockIdx.x * blockDim.x + threadIdx.x;
    if (e < EE) {
        int is64 = g_is64;
        int r = (int)eidx(ei, e, is64);
        int c = (int)eidx(ei, (long long)EE + e, is64);
        int pos = atomicAdd(&g_cursor[c], 1);
        g_csr_src[pos] = r;
        g_csr_w[pos]   = g_deg[r] * g_norm[e] * g_deg[c];
    }
}

// ---------------- GEMM: X0 = x @ W'^T  (N x 64) ------------------------------
// 128 threads, 32-node tile; thread owns 4 nodes x 4 classes (outer product).
#define GN 32
__global__ void __launch_bounds__(128) k_gemm(const float* __restrict__ x) {
    __shared__ float sWt[FF * CC];   // [k][c]  32 KB
    __shared__ float sx[GN * FF];    // row-major 16 KB
    int t = threadIdx.x;
    for (int i = t; i < FF * CC / 4; i += 128)
        ((float4*)sWt)[i] = ((const float4*)g_Wt)[i];
    size_t nbase = (size_t)blockIdx.x * GN;
    for (int i = t; i < GN * FF / 4; i += 128)
        ((float4*)sx)[i] = ((const float4*)(x + nbase * FF))[i];
    __syncthreads();

    int c4 = t & 15;          // class float4 group (classes 4*c4 .. +3)
    int n0 = (t >> 4) * 4;    // node group base (0..28)
    float4 a0 = {0,0,0,0}, a1 = {0,0,0,0}, a2 = {0,0,0,0}, a3 = {0,0,0,0};
    #pragma unroll 4
    for (int k = 0; k < FF; k++) {
        float4 w4 = ((const float4*)sWt)[k * 16 + c4];
        float x0 = sx[(n0 + 0) * FF + k];
        float x1 = sx[(n0 + 1) * FF + k];
        float x2 = sx[(n0 + 2) * FF + k];
        float x3 = sx[(n0 + 3) * FF + k];
        a0.x += x0 * w4.x; a0.y += x0 * w4.y; a0.z += x0 * w4.z; a0.w += x0 * w4.w;
        a1.x += x1 * w4.x; a1.y += x1 * w4.y; a1.z += x1 * w4.z; a1.w += x1 * w4.w;
        a2.x += x2 * w4.x; a2.y += x2 * w4.y; a2.z += x2 * w4.z; a2.w += x2 * w4.w;
        a3.x += x3 * w4.x; a3.y += x3 * w4.y; a3.z += x3 * w4.z; a3.w += x3 * w4.w;
    }
    float4* o = (float4*)g_X0;
    o[(nbase + n0 + 0) * 16 + c4] = a0;
    o[(nbase + n0 + 1) * 16 + c4] = a1;
    o[(nbase + n0 + 2) * 16 + c4] = a2;
    o[(nbase + n0 + 3) * 16 + c4] = a3;
}

// ---------------- hop: warp per node, width 64, two edges in flight ----------
// dir=0: X0->X1.  final=1: X1 -> out with fused bias + log_softmax.
__global__ void k_hop(int dir, const float* __restrict__ bias,
                      float* __restrict__ out, int final_) {
    const float4* __restrict__ sv = (const float4*)(dir ? g_X1 : g_X0);
    float4*       __restrict__ dv = (float4*)(dir ? g_X0 : g_X1);
    int warp = (blockIdx.x * blockDim.x + threadIdx.x) >> 5;
    if (warp >= NN) return;
    int lane = threadIdx.x & 31;
    int l16  = lane & 15;
    int half = lane >> 4;
    int n = warp;

    float4 acc = {0.f, 0.f, 0.f, 0.f};
    if (half == 0) {
        float d = g_deg[n];
        float dd = d * d;
        float4 v = sv[(size_t)n * 16 + l16];
        acc.x = dd * v.x; acc.y = dd * v.y; acc.z = dd * v.z; acc.w = dd * v.w;
    }
    int beg = g_rowptr[n], end = g_rowptr[n + 1];
    int e = beg + half;
    // 2-deep pipeline per half: edges e and e+2 in flight
    for (; e + 2 < end; e += 4) {
        float w0 = __ldg(&g_csr_w[e]);
        int   s0 = __ldg(&g_csr_src[e]);
        float w1 = __ldg(&g_csr_w[e + 2]);
        int   s1 = __ldg(&g_csr_src[e + 2]);
        float4 v0 = sv[(size_t)s0 * 16 + l16];
        float4 v1 = sv[(size_t)s1 * 16 + l16];
        acc.x += w0 * v0.x; acc.y += w0 * v0.y; acc.z += w0 * v0.z; acc.w += w0 * v0.w;
        acc.x += w1 * v1.x; acc.y += w1 * v1.y; acc.z += w1 * v1.z; acc.w += w1 * v1.w;
    }
    for (; e < end; e += 2) {
        float w0 = __ldg(&g_csr_w[e]);
        int   s0 = __ldg(&g_csr_src[e]);
        float4 v0 = sv[(size_t)s0 * 16 + l16];
        acc.x += w0 * v0.x; acc.y += w0 * v0.y; acc.z += w0 * v0.z; acc.w += w0 * v0.w;
    }
    // combine halves
    acc.x += __shfl_xor_sync(0xffffffffu, acc.x, 16);
    acc.y += __shfl_xor_sync(0xffffffffu, acc.y, 16);
    acc.z += __shfl_xor_sync(0xffffffffu, acc.z, 16);
    acc.w += __shfl_xor_sync(0xffffffffu, acc.w, 16);

    if (!final_) {
        if (half == 0) dv[(size_t)n * 16 + l16] = acc;
        return;
    }
    // final: bias + log_softmax over 64 classes (16 lanes x float4)
    float4 b4 = ((const float4*)bias)[l16];
    acc.x += b4.x; acc.y += b4.y; acc.z += b4.z; acc.w += b4.w;
    float m = fmaxf(fmaxf(acc.x, acc.y), fmaxf(acc.z, acc.w));
    #pragma unroll
    for (int o = 1; o < 16; o <<= 1)
        m = fmaxf(m, __shfl_xor_sync(0xffffffffu, m, o));
    float s = __expf(acc.x - m) + __expf(acc.y - m)
            + __expf(acc.z - m) + __expf(acc.w - m);
    #pragma unroll
    for (int o = 1; o < 16; o <<= 1)
        s += __shfl_xor_sync(0xffffffffu, s, o);
    float lse = m + __logf(s);
    if (half == 0) {
        float4 r;
        r.x = acc.x - lse; r.y = acc.y - lse; r.z = acc.z - lse; r.w = acc.w - lse;
        ((float4*)out)[(size_t)n * 16 + l16] = r;
    }
}

// ---------------------------------------------------------------------------
extern "C" void kernel_launch(void* const* d_in, const int* in_sizes, int n_in,
                              void* d_out, int out_size) {
    const float* x  = (const float*)d_in[0];
    const void*  ei = d_in[1];
    const float* ew = (const float*)d_in[2];
    const float* xw = (const float*)d_in[3];
    const float* W  = (const float*)d_in[4];
    const float* b  = (const float*)d_in[5];
    float* out = (float*)d_out;

    const int T = 256;

    k_detect<<<1, 256>>>((const int*)ei);
    k_feat_gate<<<1, 128>>>(xw);
    k_wprep<<<(CC * FF + T - 1) / T, T>>>(W);
    k_init<<<(NN + T - 1) / T, T>>>();
    k_edge_deg<<<(EE + T - 1) / T, T>>>(ei, ew);
    k_dinv<<<(NN + T - 1) / T, T>>>();
    k_scan<<<1, 1024>>>();
    k_fill<<<(EE + T - 1) / T, T>>>(ei);

    k_gemm<<<NN / GN, 128>>>(x);                 // X0 = (x*s) @ W^T  [N,64]

    const int HB = (NN * 32 + T - 1) / T;
    k_hop<<<HB, T>>>(0, b, out, 0);              // hop1: X0 -> X1
    k_hop<<<HB, T>>>(1, b, out, 1);              // hop2: X1 -> out (fused epi)
}